// round 9
// baseline (speedup 1.0000x reference)
#include <cuda_runtime.h>
#include <cstdint>

#define BB   64
#define CC   64
#define TT   128
#define VV   25
#define RR   8
#define TSN  9
#define OUTC 64
#define TV   (TT*VV)      // 3200

typedef unsigned long long ull;

// ---- device scratch (allocation-free contract) ----
__device__ float g_xm[BB*CC*VV];
__device__ float g_rel[BB*RR*VV*VV];
__device__ float g_z[BB*CC*TV];

__device__ __forceinline__ void fma2(ull& a, ull x, ull w){
    asm("fma.rn.f32x2 %0,%1,%2,%0;" : "+l"(a) : "l"(x), "l"(w));
}
__device__ __forceinline__ void unpack2(ull a, float& lo, float& hi){
    unsigned l, h; asm("mov.b64 {%0,%1},%2;" : "=r"(l), "=r"(h) : "l"(a));
    lo = __uint_as_float(l); hi = __uint_as_float(h);
}

// ============================================================
// K1: xm[b,c,v] = mean_t x[b,c,t,v]
// ============================================================
__global__ void k1_mean(const float* __restrict__ x) {
    int bc = blockIdx.x;
    int v  = threadIdx.x;
    if (v >= VV) return;
    const float* p = x + bc * TV + v;
    float acc = 0.f;
#pragma unroll 8
    for (int t = 0; t < TT; ++t) acc += p[t*VV];
    g_xm[bc*VV + v] = acc * (1.0f / TT);
}

// ============================================================
// K2: x1/x2 = W·xm + b ; rel[b,r,v,j] = tanh(x1[r,v] - x2[r,j])
// ============================================================
__global__ void k2_rel(const float* __restrict__ W1, const float* __restrict__ b1,
                       const float* __restrict__ W2, const float* __restrict__ b2) {
    int b   = blockIdx.x;
    int tid = threadIdx.x;
    __shared__ float s_xm[CC*VV];
    __shared__ float s_x1[RR*VV];
    __shared__ float s_x2[RR*VV];

    for (int i = tid; i < CC*VV; i += blockDim.x) s_xm[i] = g_xm[b*CC*VV + i];
    __syncthreads();

    for (int i = tid; i < RR*VV; i += blockDim.x) {
        int r = i / VV, v = i % VV;
        float a1 = b1[r], a2 = b2[r];
#pragma unroll 8
        for (int c = 0; c < CC; ++c) {
            float xv = s_xm[c*VV + v];
            a1 += W1[r*CC + c] * xv;
            a2 += W2[r*CC + c] * xv;
        }
        s_x1[i] = a1; s_x2[i] = a2;
    }
    __syncthreads();

    for (int i = tid; i < RR*VV*VV; i += blockDim.x) {
        int r   = i / (VV*VV);
        int rem = i % (VV*VV);
        int v   = rem / VV;
        int j   = rem % VV;
        g_rel[b*RR*VV*VV + i] = tanhf(s_x1[r*VV + v] - s_x2[r*VV + j]);
    }
}

// ============================================================
// K3: two channels (c0=2cp, c1=2cp+1) per CTA, c-pair-packed f32x2.
//   xs2[v][tpad] = {x_c0, x_c1};  wk2[v][k][i] = {Wk_c0, Wk_c1}
//   acc2[t][i] += xs2[v][t+k] * wk2[v][k][i]   (both channels per FFMA2)
// 160 threads: 32 t-tiles (4t) x 5 i-tiles (5i)
// ============================================================
#define XPAD 136
#define SM3_XS   (VV*XPAD)          // float2 count: 3400
#define SM3_WK   (VV*TSN*VV)        // float2 count: 5625
#define SM3_BYTES ((SM3_XS + SM3_WK)*8 + 2*TSN*RR*4 + 2*TSN*4)   // 72888

__global__ __launch_bounds__(160, 3) void k3_pack(
    const float* __restrict__ x, const float* __restrict__ Astat,
    const float* __restrict__ W4, const float* __restrict__ b4)
{
    extern __shared__ __align__(16) char sm3[];
    float2* xs2 = (float2*)sm3;                 // [25][136]
    float2* wk2 = xs2 + SM3_XS;                 // [25][9][25]
    float*  sW4 = (float*)(wk2 + SM3_WK);       // [2][9][8]
    float*  sb4 = sW4 + 2*TSN*RR;               // [2][9]

    int cp = blockIdx.x, b = blockIdx.y;
    int c0 = 2*cp;
    int tid = threadIdx.x;

    // stage W4/b4 for both channels (contiguous in memory)
    if (tid < 2*TSN*RR) sW4[tid] = W4[c0*TSN*RR + tid];
    if (tid < 2*TSN)    sb4[tid] = b4[c0*TSN + tid];

    // zero causal pad
    for (int i = tid; i < VV*(TSN-1); i += 160) {
        int v = i / (TSN-1), t = i % (TSN-1);
        xs2[v*XPAD + t] = make_float2(0.f, 0.f);
    }

    // stage x for both channels, interleaved
    const float* xp0 = x + ((size_t)b*CC + c0) * TV;
    const float* xp1 = xp0 + TV;
    for (int i = tid; i < TV; i += 160) {
        int t = i / VV, v = i - t*VV;
        xs2[v*XPAD + t + 8] = make_float2(xp0[i], xp1[i]);
    }

    // BARRIER: sW4/sb4 written by threads 0..143 must be visible to ALL
    // threads before the Wk build below (this missing sync was the R7 bug).
    __syncthreads();

    // build Wk for both channels: rel/A loads shared across the pair
    const float* relp = g_rel + (size_t)b*RR*VV*VV;
    for (int p = tid; p < VV*VV; p += 160) {
        float rl[RR];
#pragma unroll
        for (int r = 0; r < RR; ++r) rl[r] = __ldg(relp + r*VV*VV + p);
        float av = __ldg(Astat + p);
        int v = p / VV, i = p - v*VV;
#pragma unroll
        for (int k = 0; k < TSN; ++k) {
            float s0 = sb4[k]       + av;
            float s1 = sb4[TSN + k] + av;
#pragma unroll
            for (int r = 0; r < RR; ++r) {
                s0 += sW4[k*RR + r]          * rl[r];
                s1 += sW4[TSN*RR + k*RR + r] * rl[r];
            }
            wk2[(v*TSN + k)*VV + i] = make_float2(s0, s1);
        }
    }
    __syncthreads();

    // mainloop: 4t x 5i per thread, both channels packed
    int t0 = (tid / 5) * 4;
    int i0 = (tid % 5) * 5;

    ull acc[4][5];
#pragma unroll
    for (int a = 0; a < 4; ++a)
#pragma unroll
        for (int j = 0; j < 5; ++j) acc[a][j] = 0ull;

    for (int v = 0; v < VV; ++v) {
        const ull* xrow = (const ull*)(xs2 + v*XPAD + t0);
        ull xr[12];
#pragma unroll
        for (int j = 0; j < 12; ++j) xr[j] = xrow[j];
        const ull* wrow = (const ull*)(wk2 + v*TSN*VV + i0);
#pragma unroll
        for (int k = 0; k < TSN; ++k) {
            ull w[5];
#pragma unroll
            for (int j = 0; j < 5; ++j) w[j] = wrow[k*VV + j];
#pragma unroll
            for (int tt = 0; tt < 4; ++tt) {
                ull xv = xr[tt + k];
                fma2(acc[tt][0], xv, w[0]);
                fma2(acc[tt][1], xv, w[1]);
                fma2(acc[tt][2], xv, w[2]);
                fma2(acc[tt][3], xv, w[3]);
                fma2(acc[tt][4], xv, w[4]);
            }
        }
    }

    float* zp0 = g_z + ((size_t)b*CC + c0) * TV;
    float* zp1 = zp0 + TV;
#pragma unroll
    for (int tt = 0; tt < 4; ++tt)
#pragma unroll
        for (int j = 0; j < 5; ++j) {
            float lo, hi;
            unpack2(acc[tt][j], lo, hi);
            int idx = (t0 + tt)*VV + i0 + j;
            zp0[idx] = lo;
            zp1[idx] = hi;
        }
}

// ============================================================
// K4: out[b,o,n] = sum_c W3[o,c]*z[b,c,n] + b3[o]
// c-pair packing: lo lane sums even c, hi lane odd c; merge at end.
// zt2[cp][n] = {z_c0[n], z_c1[n]};  w3t2[cp][o] = {W3[o][c0], W3[o][c1]}
// ============================================================
__global__ __launch_bounds__(256, 3) void k4_out(
    const float* __restrict__ W3, const float* __restrict__ b3,
    float* __restrict__ out)
{
    int nb = blockIdx.x, b = blockIdx.y;
    int n0 = nb * 128, tid = threadIdx.x;
    __shared__ __align__(16) float2 zt2[CC/2][128];    // 32 KB
    __shared__ __align__(16) float2 w3t2[CC/2][OUTC];  // 16 KB

    const float* zb = g_z + (size_t)b*CC*TV;
    for (int i = tid; i < CC*128; i += 256) {
        int c = i >> 7, n = i & 127;
        ((float*)&zt2[c >> 1][n])[c & 1] = zb[(size_t)c*TV + n0 + n];
    }
    for (int i = tid; i < OUTC*CC; i += 256) {
        int o = i >> 6, c = i & 63;
        ((float*)&w3t2[c >> 1][o])[c & 1] = W3[o*CC + c];
    }
    __syncthreads();

    int o0 = (tid >> 5) * 8;
    int nl = (tid & 31) * 4;

    ull acc[8][4];
#pragma unroll
    for (int o = 0; o < 8; ++o)
#pragma unroll
        for (int n = 0; n < 4; ++n) acc[o][n] = 0ull;

    for (int cpi = 0; cpi < CC/2; ++cpi) {
        ull zv[4];
        const ull* zrow = (const ull*)&zt2[cpi][nl];
#pragma unroll
        for (int n = 0; n < 4; ++n) zv[n] = zrow[n];
        ull wv[8];
        const ull* wrow = (const ull*)&w3t2[cpi][o0];
#pragma unroll
        for (int o = 0; o < 8; ++o) wv[o] = wrow[o];
#pragma unroll
        for (int o = 0; o < 8; ++o) {
            fma2(acc[o][0], wv[o], zv[0]);
            fma2(acc[o][1], wv[o], zv[1]);
            fma2(acc[o][2], wv[o], zv[2]);
            fma2(acc[o][3], wv[o], zv[3]);
        }
    }

#pragma unroll
    for (int o = 0; o < 8; ++o) {
        float bias = b3[o0 + o];
        float4 r;
        float lo, hi;
        unpack2(acc[o][0], lo, hi); r.x = lo + hi + bias;
        unpack2(acc[o][1], lo, hi); r.y = lo + hi + bias;
        unpack2(acc[o][2], lo, hi); r.z = lo + hi + bias;
        unpack2(acc[o][3], lo, hi); r.w = lo + hi + bias;
        *(float4*)&out[((size_t)b*OUTC + o0 + o)*TV + n0 + nl] = r;
    }
}

// ============================================================
extern "C" void kernel_launch(void* const* d_in, const int* in_sizes, int n_in,
                              void* d_out, int out_size) {
    const float* x  = (const float*)d_in[0];
    const float* A  = (const float*)d_in[1];
    const float* W1 = (const float*)d_in[2];
    const float* b1 = (const float*)d_in[3];
    const float* W2 = (const float*)d_in[4];
    const float* b2 = (const float*)d_in[5];
    const float* W4 = (const float*)d_in[6];
    const float* b4 = (const float*)d_in[7];
    const float* W3 = (const float*)d_in[8];
    const float* b3 = (const float*)d_in[9];
    float* out = (float*)d_out;

    static bool attr_set = false;
    if (!attr_set) {
        cudaFuncSetAttribute(k3_pack, cudaFuncAttributeMaxDynamicSharedMemorySize, SM3_BYTES);
        attr_set = true;
    }

    k1_mean<<<BB*CC, 32>>>(x);
    k2_rel<<<BB, 256>>>(W1, b1, W2, b2);
    k3_pack<<<dim3(CC/2, BB), 160, SM3_BYTES>>>(x, A, W4, b4);
    k4_out<<<dim3(TV/128, BB), 256>>>(W3, b3, out);
}

// round 10
// speedup vs baseline: 1.0300x; 1.0300x over previous
#include <cuda_runtime.h>
#include <cstdint>

#define BB   64
#define CC   64
#define TT   128
#define VV   25
#define RR   8
#define TSN  9
#define OUTC 64
#define TV   (TT*VV)      // 3200
#define XPAD (TT+TSN-1)   // 136

// ---- device scratch (allocation-free contract) ----
__device__ float g_xm[BB*CC*VV];
__device__ float g_rel[BB*RR*VV*VV];
__device__ float g_z[BB*CC*TV];

// ============================================================
// K1: xm[b,c,v] = mean_t x[b,c,t,v]
// ============================================================
__global__ void k1_mean(const float* __restrict__ x) {
    int bc = blockIdx.x;
    int v  = threadIdx.x;
    if (v >= VV) return;
    const float* p = x + bc * TV + v;
    float acc = 0.f;
#pragma unroll 8
    for (int t = 0; t < TT; ++t) acc += p[t*VV];
    g_xm[bc*VV + v] = acc * (1.0f / TT);
}

// ============================================================
// K2: x1/x2 = W·xm + b ; rel[b,r,v,j] = tanh(x1[r,v] - x2[r,j])
// ============================================================
__global__ void k2_rel(const float* __restrict__ W1, const float* __restrict__ b1,
                       const float* __restrict__ W2, const float* __restrict__ b2) {
    int b   = blockIdx.x;
    int tid = threadIdx.x;
    __shared__ float s_xm[CC*VV];
    __shared__ float s_x1[RR*VV];
    __shared__ float s_x2[RR*VV];

    for (int i = tid; i < CC*VV; i += blockDim.x) s_xm[i] = g_xm[b*CC*VV + i];
    __syncthreads();

    for (int i = tid; i < RR*VV; i += blockDim.x) {
        int r = i / VV, v = i % VV;
        float a1 = b1[r], a2 = b2[r];
#pragma unroll 8
        for (int c = 0; c < CC; ++c) {
            float xv = s_xm[c*VV + v];
            a1 += W1[r*CC + c] * xv;
            a2 += W2[r*CC + c] * xv;
        }
        s_x1[i] = a1; s_x2[i] = a2;
    }
    __syncthreads();

    for (int i = tid; i < RR*VV*VV; i += blockDim.x) {
        int r   = i / (VV*VV);
        int rem = i % (VV*VV);
        int v   = rem / VV;
        int j   = rem % VV;
        g_rel[b*RR*VV*VV + i] = tanhf(s_x1[r*VV + v] - s_x2[r*VV + j]);
    }
}

// ============================================================
// K3 (R1 scalar, known-good 190us): per (b,c):
//   Wk[v,k,i] = A[v,i] + b4[c*9+k] + sum_r W4[c*9+k,r]*rel[b,r,v,i]
//   z[t,i] = sum_{v,k} xs[v][t+k] * Wk[v,k,i]
// 160 threads: 32 t-tiles (4t) x 5 i-tiles (5i)
// ============================================================
__global__ __launch_bounds__(160) void k3_main(
    const float* __restrict__ x, const float* __restrict__ A,
    const float* __restrict__ W4, const float* __restrict__ b4) {

    int c = blockIdx.x;
    int b = blockIdx.y;
    int tid = threadIdx.x;

    __shared__ __align__(16) float xs[VV][XPAD];     // 13.6 KB
    __shared__ float wk[VV][TSN][VV];                // 22.5 KB
    __shared__ float sW4[TSN*RR];
    __shared__ float sb4[TSN];

    if (tid < TSN*RR) sW4[tid] = W4[c*TSN*RR + tid];
    if (tid < TSN)    sb4[tid] = b4[c*TSN + tid];

    const float* xp = x + (b*CC + c) * TV;
    for (int i = tid; i < TV; i += 160) {
        int t = i / VV, v = i % VV;
        xs[v][t + TSN - 1] = xp[i];
    }
    for (int i = tid; i < VV*(TSN-1); i += 160) {
        xs[i / (TSN-1)][i % (TSN-1)] = 0.f;
    }
    __syncthreads();

    for (int it = tid; it < VV*VV; it += 160) {
        int v = it / VV, i = it % VV;
        float rl[RR];
        const float* rp = g_rel + (b*RR*VV + v)*VV + i;
#pragma unroll
        for (int r = 0; r < RR; ++r) rl[r] = rp[r*VV*VV];
        float av = A[v*VV + i];
#pragma unroll
        for (int k = 0; k < TSN; ++k) {
            float s = sb4[k] + av;
#pragma unroll
            for (int r = 0; r < RR; ++r) s += sW4[k*RR + r] * rl[r];
            wk[v][k][i] = s;
        }
    }
    __syncthreads();

    int t0 = (tid / 5) * 4;
    int i0 = (tid % 5) * 5;

    float acc[4][5];
#pragma unroll
    for (int a = 0; a < 4; ++a)
#pragma unroll
        for (int j = 0; j < 5; ++j) acc[a][j] = 0.f;

    for (int v = 0; v < VV; ++v) {
        const float4* xv4 = reinterpret_cast<const float4*>(&xs[v][t0]);
        float4 q0 = xv4[0], q1 = xv4[1], q2 = xv4[2];
        float xr[12] = {q0.x,q0.y,q0.z,q0.w, q1.x,q1.y,q1.z,q1.w, q2.x,q2.y,q2.z,q2.w};
#pragma unroll
        for (int k = 0; k < TSN; ++k) {
            float w0 = wk[v][k][i0+0];
            float w1 = wk[v][k][i0+1];
            float w2 = wk[v][k][i0+2];
            float w3 = wk[v][k][i0+3];
            float w4 = wk[v][k][i0+4];
#pragma unroll
            for (int tt = 0; tt < 4; ++tt) {
                float xv = xr[tt + k];
                acc[tt][0] += xv * w0;
                acc[tt][1] += xv * w1;
                acc[tt][2] += xv * w2;
                acc[tt][3] += xv * w3;
                acc[tt][4] += xv * w4;
            }
        }
    }

    float* zp = g_z + (b*CC + c) * TV;
#pragma unroll
    for (int tt = 0; tt < 4; ++tt)
#pragma unroll
        for (int j = 0; j < 5; ++j)
            zp[(t0 + tt)*VV + i0 + j] = acc[tt][j];
}

// ============================================================
// K4: out[b,o,n] = sum_c W3[o,c]*z[b,c,n] + b3[o]
// 128 threads, 8o x 8n per thread; W3 staged TRANSPOSED [c][o] so both
// operands are LDS.128 (w-loads warp-uniform -> broadcast).
// Per c-step: 4 LDS.128 + 64 FFMA  (94% FMA mix)
// ============================================================
__global__ __launch_bounds__(128) void k4_out(
    const float* __restrict__ W3, const float* __restrict__ b3,
    float* __restrict__ out)
{
    int nb = blockIdx.x;          // 0..24
    int b  = blockIdx.y;
    int n0 = nb * 128;
    int tid = threadIdx.x;

    __shared__ __align__(16) float zt[CC][128];     // 32 KB
    __shared__ __align__(16) float w3t[CC][OUTC];   // 16 KB  (48 KB total)

    const float* zb = g_z + (size_t)b*CC*TV;
    for (int i = tid; i < CC*128; i += 128) {
        int c = i >> 7, n = i & 127;
        zt[c][n] = zb[(size_t)c*TV + n0 + n];
    }
    // transpose-stage W3: lanes write consecutive o (conflict-free STS);
    // gmem reads strided but W3 is 16KB and L2-hot after wave 1.
    for (int i = tid; i < CC*OUTC; i += 128) {
        int c = i >> 6, o = i & 63;
        w3t[c][o] = W3[o*CC + c];
    }
    __syncthreads();

    int o0 = (tid >> 4) * 8;      // 8 o-tiles
    int nl = (tid & 15) * 8;      // 16 n-tiles

    float acc[8][8];
#pragma unroll
    for (int o = 0; o < 8; ++o)
#pragma unroll
        for (int n = 0; n < 8; ++n) acc[o][n] = 0.f;

    for (int c = 0; c < CC; ++c) {
        float4 z0 = *(const float4*)&zt[c][nl];
        float4 z1 = *(const float4*)&zt[c][nl + 4];
        float4 w0 = *(const float4*)&w3t[c][o0];
        float4 w1 = *(const float4*)&w3t[c][o0 + 4];
        float zv[8] = {z0.x, z0.y, z0.z, z0.w, z1.x, z1.y, z1.z, z1.w};
        float wv[8] = {w0.x, w0.y, w0.z, w0.w, w1.x, w1.y, w1.z, w1.w};
#pragma unroll
        for (int o = 0; o < 8; ++o)
#pragma unroll
            for (int n = 0; n < 8; ++n)
                acc[o][n] += wv[o] * zv[n];
    }

#pragma unroll
    for (int o = 0; o < 8; ++o) {
        float bias = b3[o0 + o];
        float4 r0, r1;
        r0.x = acc[o][0] + bias;  r0.y = acc[o][1] + bias;
        r0.z = acc[o][2] + bias;  r0.w = acc[o][3] + bias;
        r1.x = acc[o][4] + bias;  r1.y = acc[o][5] + bias;
        r1.z = acc[o][6] + bias;  r1.w = acc[o][7] + bias;
        float* op = &out[((size_t)b*OUTC + o0 + o)*TV + n0 + nl];
        *(float4*)op       = r0;
        *(float4*)(op + 4) = r1;
    }
}

// ============================================================
extern "C" void kernel_launch(void* const* d_in, const int* in_sizes, int n_in,
                              void* d_out, int out_size) {
    const float* x  = (const float*)d_in[0];
    const float* A  = (const float*)d_in[1];
    const float* W1 = (const float*)d_in[2];
    const float* b1 = (const float*)d_in[3];
    const float* W2 = (const float*)d_in[4];
    const float* b2 = (const float*)d_in[5];
    const float* W4 = (const float*)d_in[6];
    const float* b4 = (const float*)d_in[7];
    const float* W3 = (const float*)d_in[8];
    const float* b3 = (const float*)d_in[9];
    float* out = (float*)d_out;

    k1_mean<<<BB*CC, 32>>>(x);
    k2_rel<<<BB, 256>>>(W1, b1, W2, b2);
    k3_main<<<dim3(CC, BB), 160>>>(x, A, W4, b4);
    k4_out<<<dim3(TV/128, BB), 128>>>(W3, b3, out);
}